// round 1
// baseline (speedup 1.0000x reference)
#include <cuda_runtime.h>

// SoftDTW-style scan: out[b,0,:] = x[b,0,:]
// out[b,t,j] = x[b,t,j] + soft(out[b,t-1,j], out[b,t-1,j-1])
//   soft(a,b) = p*a + (1-p)*b, p = sigmoid(a-b);  column 0 uses 'a' directly.
//
// Mapping: 1 CTA per batch (32 CTAs, 1024 threads). Each thread owns 2
// adjacent columns in registers. Per step the only communication is each
// thread's right column -> right neighbor, done via a double-buffered smem
// slot with one __syncthreads per step. x rows are register-prefetched
// PF=3 steps ahead to hide DRAM latency under the ~250-cycle step time.

#define SEQ_T 1024
#define COLS  2048
#define NT    1024
#define PF    3        // 1023 = 3 * 341, divides evenly

__global__ __launch_bounds__(NT, 1)
void softdtw_scan_kernel(const float* __restrict__ x, float* __restrict__ out)
{
    __shared__ float buf[2][NT];

    const int b   = blockIdx.x;
    const int tid = threadIdx.x;

    const size_t base = (size_t)b * SEQ_T * COLS + (size_t)tid * 2;
    const float* xb = x + base;
    float*       ob = out + base;

    // t = 0: carry = x row 0, emit it.
    float2 cr = __ldg((const float2*)xb);
    *(float2*)ob = cr;
    float c0 = cr.x, c1 = cr.y;

    // Prefetch x rows 1..PF into registers.
    float2 xf[PF];
#pragma unroll
    for (int i = 0; i < PF; i++)
        xf[i] = __ldg((const float2*)(xb + (size_t)(1 + i) * COLS));

    for (int t = 1; t < SEQ_T; t += PF) {
#pragma unroll
        for (int i = 0; i < PF; i++) {
            const int tt  = t + i;
            const int par = tt & 1;

            // Boundary exchange: publish my right column, read left neighbor's.
            buf[par][tid] = c1;
            __syncthreads();
            const float left = buf[par][(tid - 1) & (NT - 1)]; // tid==0 value unused

            const float2 xv = xf[i];
            // Refill prefetch slot PF steps ahead.
            if (tt + PF < SEQ_T)
                xf[i] = __ldg((const float2*)(xb + (size_t)(tt + PF) * COLS));

            // Element 0 of this thread: a = c0, b = left
            float d0 = c0 - left;
            float p0 = __fdividef(1.0f, 1.0f + __expf(-d0));
            float s0 = fmaf(d0, p0, left);          // b + p*(a-b)
            if (tid == 0) s0 = c0;                  // global column 0: use a

            // Element 1: a = c1, b = c0 (old)
            float d1 = c1 - c0;
            float p1 = __fdividef(1.0f, 1.0f + __expf(-d1));
            float s1 = fmaf(d1, p1, c0);

            c0 = s0 + xv.x;
            c1 = s1 + xv.y;

            *(float2*)(ob + (size_t)tt * COLS) = make_float2(c0, c1);
        }
    }
}

extern "C" void kernel_launch(void* const* d_in, const int* in_sizes, int n_in,
                              void* d_out, int out_size)
{
    (void)in_sizes; (void)n_in; (void)out_size;
    const float* x  = (const float*)d_in[0];
    float*       o  = (float*)d_out;
    softdtw_scan_kernel<<<32, NT>>>(x, o);
}